// round 10
// baseline (speedup 1.0000x reference)
#include <cuda_runtime.h>

// IF spiking neuron forward, non-align branch, T=4.
// x: [T*B, 1024, 3072] f32, thresh2/dtmem: [1024, 3072] f32
// out: [T*B, 1024, 3072] f32
//
// Per (b,i,j): mem = dtmem*thr; for t: mem += x_t; s = (mem>=thr)?thr:0; mem -= s; out_t = s.
//
// R10 = R5..R9 resubmitted (none ran: broker timeouts).
// Change vs R4 (last measured, 120.3us kernel / dram 82.8%): 2 float4 chains
// per thread, all 8 x-loads front-batched (MLP 4 -> 8) to close the
// dram-utilization gap. Keeps R4's streaming hints (__ldcs / __stcs) that cut
// traffic to ~790 MB.

#define T_STEPS 4
#define BATCH        8
#define FEAT_ELEMS   (1024 * 3072)          // 3,145,728
#define FEAT4        (FEAT_ELEMS / 4)       // 786,432 float4 per feature map
#define CHAIN4       (BATCH * FEAT4)        // 6,291,456 float4 chains per timestep
#define PER_THREAD   2                      // float4 chains per thread

__global__ void __launch_bounds__(256) if_fwd_kernel(
    const float4* __restrict__ x,
    const float4* __restrict__ th,
    const float4* __restrict__ dt,
    float4* __restrict__ out)
{
    // Each thread owns 2 adjacent float4s. Warp covers 2*32*16 = 1024B per
    // load pair (contiguous), fully coalesced.
    const int f0  = (blockIdx.x * blockDim.x + threadIdx.x) * PER_THREAD; // 0..FEAT4-2
    const int b   = blockIdx.y;                                           // 0..BATCH-1
    const size_t idx0 = (size_t)b * FEAT4 + f0;

    // Params: default policy -> L2-resident (8x reuse across batch)
    float4 thr[PER_THREAD], d[PER_THREAD];
#pragma unroll
    for (int c = 0; c < PER_THREAD; c++) {
        thr[c] = __ldg(&th[f0 + c]);
        d[c]   = __ldg(&dt[f0 + c]);
    }

    float4 mem[PER_THREAD];
#pragma unroll
    for (int c = 0; c < PER_THREAD; c++) {
        mem[c].x = d[c].x * thr[c].x;
        mem[c].y = d[c].y * thr[c].y;
        mem[c].z = d[c].z * thr[c].z;
        mem[c].w = d[c].w * thr[c].w;
    }

    // Front-batch all T*PER_THREAD = 8 independent streaming loads (MLP=8)
    float4 xv[T_STEPS][PER_THREAD];
#pragma unroll
    for (int t = 0; t < T_STEPS; t++) {
#pragma unroll
        for (int c = 0; c < PER_THREAD; c++) {
            xv[t][c] = __ldcs(&x[(size_t)t * CHAIN4 + idx0 + c]);
        }
    }

#pragma unroll
    for (int t = 0; t < T_STEPS; t++) {
#pragma unroll
        for (int c = 0; c < PER_THREAD; c++) {
            float4 s;
            mem[c].x += xv[t][c].x;  s.x = (mem[c].x >= thr[c].x) ? thr[c].x : 0.0f;  mem[c].x -= s.x;
            mem[c].y += xv[t][c].y;  s.y = (mem[c].y >= thr[c].y) ? thr[c].y : 0.0f;  mem[c].y -= s.y;
            mem[c].z += xv[t][c].z;  s.z = (mem[c].z >= thr[c].z) ? thr[c].z : 0.0f;  mem[c].z -= s.z;
            mem[c].w += xv[t][c].w;  s.w = (mem[c].w >= thr[c].w) ? thr[c].w : 0.0f;  mem[c].w -= s.w;
            __stcs(&out[(size_t)t * CHAIN4 + idx0 + c], s);
        }
    }
}

extern "C" void kernel_launch(void* const* d_in, const int* in_sizes, int n_in,
                              void* d_out, int out_size)
{
    const float4* x  = (const float4*)d_in[0];   // [T*B, 1024, 3072]
    const float4* th = (const float4*)d_in[1];   // thresh2 [1024, 3072]
    const float4* dt = (const float4*)d_in[2];   // dtmem   [1024, 3072]
    float4*       o  = (float4*)d_out;

    dim3 threads(256, 1, 1);
    dim3 blocks(FEAT4 / (256 * PER_THREAD), BATCH, 1);   // 1536 x 8 = 12,288 CTAs, no tail
    if_fwd_kernel<<<blocks, threads>>>(x, th, dt, o);
}

// round 13
// speedup vs baseline: 1.0491x; 1.0491x over previous
#include <cuda_runtime.h>

// IF spiking neuron forward, non-align branch, T=4.
// x: [T*B, 1024, 3072] f32, thresh2/dtmem: [1024, 3072] f32
// out: [T*B, 1024, 3072] f32
//
// Per (b,i,j): mem = dtmem*thr; for t: mem += x_t; s = (mem>=thr)?thr:0; mem -= s; out_t = s.
//
// R13 = R11/R12 resubmitted (broker timeouts, never ran).
// vs R4 (best measured: 120.3us kernel, dram 82.8%): same shape
// (PER_THREAD=1, 32 regs, 8 CTA/SM; R10's PER_THREAD=2 regressed to 127.7us
// via occ 51.9%), same __ldcs/__stcs (traffic ~790 MB), ONE tweak:
// compute all 4 spikes in-place over xv[] then issue the 4 STG.128
// back-to-back (longer write bursts, fewer DRAM R/W turnarounds),
// register-neutral via __launch_bounds__(256, 8).

#define T_STEPS 4
#define BATCH        8
#define FEAT_ELEMS   (1024 * 3072)          // 3,145,728
#define FEAT4        (FEAT_ELEMS / 4)       // 786,432 float4 per feature map
#define CHAIN4       (BATCH * FEAT4)        // 6,291,456 float4 chains per timestep

__global__ void __launch_bounds__(256, 8) if_fwd_kernel(
    const float4* __restrict__ x,
    const float4* __restrict__ th,
    const float4* __restrict__ dt,
    float4* __restrict__ out)
{
    const int f   = blockIdx.x * blockDim.x + threadIdx.x;   // 0 .. FEAT4-1
    const int b   = blockIdx.y;                              // 0 .. BATCH-1
    const size_t idx = (size_t)b * FEAT4 + f;

    // Params: default policy -> L2-resident (8x reuse across batch)
    const float4 thr = __ldg(&th[f]);
    const float4 d   = __ldg(&dt[f]);

    float4 mem;
    mem.x = d.x * thr.x;
    mem.y = d.y * thr.y;
    mem.z = d.z * thr.z;
    mem.w = d.w * thr.w;

    // Front-batch all 4 independent streaming loads (MLP=4, evict-first)
    float4 xv[T_STEPS];
#pragma unroll
    for (int t = 0; t < T_STEPS; t++) {
        xv[t] = __ldcs(&x[(size_t)t * CHAIN4 + idx]);
    }

    // Integrate-and-fire; spike overwrites the consumed input in place
    // (keeps register pressure at the R4 level -> 8 CTA/SM).
#pragma unroll
    for (int t = 0; t < T_STEPS; t++) {
        float s;
        mem.x += xv[t].x;  s = (mem.x >= thr.x) ? thr.x : 0.0f;  mem.x -= s;  xv[t].x = s;
        mem.y += xv[t].y;  s = (mem.y >= thr.y) ? thr.y : 0.0f;  mem.y -= s;  xv[t].y = s;
        mem.z += xv[t].z;  s = (mem.z >= thr.z) ? thr.z : 0.0f;  mem.z -= s;  xv[t].z = s;
        mem.w += xv[t].w;  s = (mem.w >= thr.w) ? thr.w : 0.0f;  mem.w -= s;  xv[t].w = s;
    }

    // Back-to-back streaming stores (batched write burst)
#pragma unroll
    for (int t = 0; t < T_STEPS; t++) {
        __stcs(&out[(size_t)t * CHAIN4 + idx], xv[t]);
    }
}

extern "C" void kernel_launch(void* const* d_in, const int* in_sizes, int n_in,
                              void* d_out, int out_size)
{
    const float4* x  = (const float4*)d_in[0];   // [T*B, 1024, 3072]
    const float4* th = (const float4*)d_in[1];   // thresh2 [1024, 3072]
    const float4* dt = (const float4*)d_in[2];   // dtmem   [1024, 3072]
    float4*       o  = (float4*)d_out;

    dim3 threads(256, 1, 1);
    dim3 blocks(FEAT4 / 256, BATCH, 1);          // 3072 x 8 = 24,576 CTAs, no tail
    if_fwd_kernel<<<blocks, threads>>>(x, th, dt, o);
}